// round 8
// baseline (speedup 1.0000x reference)
#include <cuda_runtime.h>
#include <cuda_bf16.h>

// Problem constants (fixed shapes from reference)
#define NN 25000
#define PP 400000
#define FF 224      // = TF = TH*FH
#define KK 32
#define HH 4
#define THH 7
#define DV 56
#define NORD 15

#define EPB 64     // edges per block
#define TPB 224    // threads per block (edge kernel)
#define CT 16      // c-tile rows staged in smem
#define HP 68      // Hs row pitch (padded; 16B aligned, stride-4 banks)

// -------- scratch (static device arrays; no allocation allowed) --------
__device__ float g_q[NN * FF];
__device__ float g_k[NN * FF];
__device__ float g_v[NN * FF];

__device__ __forceinline__ float silu_f(float x) {
    return x / (1.0f + __expf(-x));
}

// -------- per-node q,k,v precompute + output zeroing --------
__global__ __launch_bounds__(224) void node_kernel(
    const float* __restrict__ x,
    const float* __restrict__ Wq,
    const float* __restrict__ Wk,
    const float* __restrict__ Wv,
    float* __restrict__ out_x,
    float* __restrict__ out_ev)
{
    __shared__ float xs[FF];
    int n = blockIdx.x;
    int f = threadIdx.x;
    xs[f] = x[n * FF + f];
    // zero outputs (atomics accumulate into them later)
    out_x[(size_t)n * FF + f] = 0.0f;
    if (f < NORD) out_ev[(size_t)n * NORD + f] = 0.0f;
    __syncthreads();

    // q / k
    {
        int t = f >> 5;
        int i = f & 31;
        const float* wq = Wq + (t * 32 + i) * 32;
        const float* wk = Wk + (t * 32 + i) * 32;
        const float* xb = xs + t * 32;
        float aq = 0.f, ak = 0.f;
#pragma unroll
        for (int j = 0; j < 32; j++) {
            float xv = xb[j];
            aq = fmaf(__ldg(&wq[j]), xv, aq);
            ak = fmaf(__ldg(&wk[j]), xv, ak);
        }
        g_q[n * FF + f] = silu_f(aq);
        g_k[n * FF + f] = silu_f(ak);
    }
    // v
    {
        int h = f / DV;
        int i = f % DV;
        const float* wv = Wv + (h * DV + i) * DV;
        const float* xb = xs + h * DV;
        float av = 0.f;
#pragma unroll 8
        for (int j = 0; j < DV; j++) av = fmaf(__ldg(&wv[j]), xb[j], av);
        g_v[n * FF + f] = av;
    }
}

// -------- edge kernel --------
// dyn smem: w2s [CT][224] then Hs [224][HP]
extern "C" __global__ void __launch_bounds__(TPB, 2) edge_kernel(
    const float* __restrict__ rbf,
    const float* __restrict__ ylm,
    const float* __restrict__ cut,
    const int*   __restrict__ idx_i,
    const int*   __restrict__ idx_j,
    const float* __restrict__ ev,
    const float* __restrict__ W1r, const float* __restrict__ b1r,
    const float* __restrict__ W2r, const float* __restrict__ b2r,
    const float* __restrict__ W1s, const float* __restrict__ b1s,
    const float* __restrict__ W2s, const float* __restrict__ b2s,
    float* __restrict__ out_x, float* __restrict__ out_ev)
{
    extern __shared__ float dyn[];
    float* w2s = dyn;                 // CT * FF
    float* Hs  = dyn + CT * FF;       // 224 * HP  (c-major, padded)

    __shared__ float rbfc[EPB][KK];
    __shared__ float con_s[EPB][3];
    __shared__ float alpha_s[EPB][THH];
    __shared__ float ylm_s[EPB][NORD];
    __shared__ int   ii_s[EPB], jj_s[EPB];
    __shared__ float cut_s[EPB];

    const int tid = threadIdx.x;
    const int p0  = blockIdx.x * EPB;

    if (tid < EPB) {
        int p = p0 + tid;
        ii_s[tid]  = idx_i[p];
        jj_s[tid]  = idx_j[p];
        cut_s[tid] = cut[p];
    }
    for (int idx = tid; idx < EPB * THH; idx += TPB)
        ((float*)alpha_s)[idx] = 0.0f;
    __syncthreads();

    // rbf * cut into smem
    for (int idx = tid; idx < EPB * KK; idx += TPB) {
        int e = idx >> 5, kk = idx & 31;
        rbfc[e][kk] = rbf[(p0 + e) * KK + kk] * cut_s[e];
    }
    // ylm into smem
    for (int idx = tid; idx < EPB * NORD; idx += TPB) {
        int e = idx / NORD, o = idx % NORD;
        ylm_s[e][o] = ylm[(p0 + e) * NORD + o];
    }
    // l0 contraction per edge
    if (tid < EPB) {
        int e = tid;
        const float* evi = ev + (size_t)ii_s[e] * NORD;
        const float* evj = ev + (size_t)jj_s[e] * NORD;
        float c0 = 0.f, c1 = 0.f, c2 = 0.f;
#pragma unroll
        for (int o = 0; o < 3; o++)  { float d = __ldg(&evj[o]) - __ldg(&evi[o]); c0 = fmaf(d, d, c0); }
#pragma unroll
        for (int o = 3; o < 8; o++)  { float d = __ldg(&evj[o]) - __ldg(&evi[o]); c1 = fmaf(d, d, c1); }
#pragma unroll
        for (int o = 8; o < 15; o++) { float d = __ldg(&evj[o]) - __ldg(&evi[o]); c2 = fmaf(d, d, c2); }
        con_s[e][0] = c0; con_s[e][1] = c1; con_s[e][2] = c2;
    }
    __syncthreads();

    // ---- H compute ----
    // Thread owns fixed c = tid % 112; visits 32 edges (e = 2k + (tid>=112)).
    {
        const int cH = tid % 112;
        const int eBase = (tid >= 112) ? 1 : 0;
        float w1rr[32];
#pragma unroll
        for (int kk = 0; kk < 32; kk++) w1rr[kk] = __ldg(&W1r[kk * 112 + cH]);
        const float w1s0 = __ldg(&W1s[cH]);
        const float w1s1 = __ldg(&W1s[112 + cH]);
        const float w1s2 = __ldg(&W1s[224 + cH]);
        const float b1rc = __ldg(&b1r[cH]);
        const float b1sc = __ldg(&b1s[cH]);
#pragma unroll 4
        for (int k2 = 0; k2 < EPB / 2; k2++) {
            const int e = 2 * k2 + eBase;
            const float4* r4 = (const float4*)&rbfc[e][0];
            float a1 = b1rc;
#pragma unroll
            for (int q = 0; q < 8; q++) {
                float4 rv = r4[q];
                a1 = fmaf(rv.x, w1rr[4 * q + 0], a1);
                a1 = fmaf(rv.y, w1rr[4 * q + 1], a1);
                a1 = fmaf(rv.z, w1rr[4 * q + 2], a1);
                a1 = fmaf(rv.w, w1rr[4 * q + 3], a1);
            }
            float a2 = b1sc;
            a2 = fmaf(con_s[e][0], w1s0, a2);
            a2 = fmaf(con_s[e][1], w1s1, a2);
            a2 = fmaf(con_s[e][2], w1s2, a2);
            Hs[cH * HP + e]         = silu_f(a1);
            Hs[(cH + 112) * HP + e] = silu_f(a2);
        }
    }

    // ---- main trilinear: wsum[e, f] = sum_c H[e,c] * W2cat[c,f] ----
    // thread tiling: 8 edge-groups (8 edges each) x 28 column-chunks
    const int eg    = tid / 28;       // 0..7
    const int chunk = tid % 28;       // 0..27
    const int e0 = eg * 8;
    const int f0 = chunk * 4;         // 0..108
    const int hA = f0 >> 5;           // 0..3
    const int hB = (f0 + 112) >> 5;   // 3..6

    float acc[8][8];
    {
        float b2c[8];
#pragma unroll
        for (int u = 0; u < 4; u++) {
            b2c[u]     = __ldg(&b2r[f0 + u])       + __ldg(&b2s[f0 + u]);
            b2c[4 + u] = __ldg(&b2r[f0 + 112 + u]) + __ldg(&b2s[f0 + 112 + u]);
        }
#pragma unroll
        for (int e = 0; e < 8; e++)
#pragma unroll
            for (int u = 0; u < 8; u++) acc[e][u] = b2c[u];
    }

#pragma unroll 1
    for (int ct = 0; ct < FF / CT; ct++) {
        __syncthreads();   // w2s reuse + (first iter) Hs completion
        // stage W2cat rows [ct*CT, ct*CT+CT) — float4 vectorized
        for (int idx = tid; idx < CT * (FF / 4); idx += TPB) {
            int cl = idx / (FF / 4);
            int f4 = idx % (FF / 4);
            int cg = ct * CT + cl;
            const float4* src = (cg < 112)
                ? (const float4*)(W2r + (size_t)cg * FF)
                : (const float4*)(W2s + (size_t)(cg - 112) * FF);
            ((float4*)(w2s + cl * FF))[f4] = __ldg(&src[f4]);
        }
        __syncthreads();
        const float* hbase = Hs + (ct * CT) * HP + e0;
        const float* wbase = w2s + f0;
#pragma unroll 4
        for (int cl = 0; cl < CT; cl++) {
            float4 w0 = *(const float4*)(wbase + cl * FF);
            float4 w1 = *(const float4*)(wbase + cl * FF + 112);
            float4 ha = *(const float4*)(hbase + cl * HP);
            float4 hb = *(const float4*)(hbase + cl * HP + 4);
            float hv[8] = {ha.x, ha.y, ha.z, ha.w, hb.x, hb.y, hb.z, hb.w};
#pragma unroll
            for (int e = 0; e < 8; e++) {
                acc[e][0] = fmaf(hv[e], w0.x, acc[e][0]);
                acc[e][1] = fmaf(hv[e], w0.y, acc[e][1]);
                acc[e][2] = fmaf(hv[e], w0.z, acc[e][2]);
                acc[e][3] = fmaf(hv[e], w0.w, acc[e][3]);
                acc[e][4] = fmaf(hv[e], w1.x, acc[e][4]);
                acc[e][5] = fmaf(hv[e], w1.y, acc[e][5]);
                acc[e][6] = fmaf(hv[e], w1.z, acc[e][6]);
                acc[e][7] = fmaf(hv[e], w1.w, acc[e][7]);
            }
        }
    }

    // ---- apply G = q_i * k_j elementwise, reduce over the 8 owned columns ----
#pragma unroll 2
    for (int e = 0; e < 8; e++) {
        const size_t ri = (size_t)ii_s[e0 + e] * FF;
        const size_t rj = (size_t)jj_s[e0 + e] * FF;
        float4 qa = *(const float4*)&g_q[ri + f0];
        float4 qb = *(const float4*)&g_q[ri + f0 + 112];
        float4 ka = *(const float4*)&g_k[rj + f0];
        float4 kb = *(const float4*)&g_k[rj + f0 + 112];
        float aA = acc[e][0] * (qa.x * ka.x);
        aA = fmaf(acc[e][1], qa.y * ka.y, aA);
        aA = fmaf(acc[e][2], qa.z * ka.z, aA);
        aA = fmaf(acc[e][3], qa.w * ka.w, aA);
        float aB = acc[e][4] * (qb.x * kb.x);
        aB = fmaf(acc[e][5], qb.y * kb.y, aB);
        aB = fmaf(acc[e][6], qb.z * kb.z, aB);
        aB = fmaf(acc[e][7], qb.w * kb.w, aB);
        atomicAdd(&alpha_s[e0 + e][hA], aA);
        atomicAdd(&alpha_s[e0 + e][hB], aB);
    }
    __syncthreads();

    // ---- scatter x_att: thread f owns output column f; run-length aggregate over sorted i
    {
        int f = tid;                 // 0..223
        int hh = f / DV;             // 0..3
        float run = 0.f;
        int iprev = ii_s[0];
#pragma unroll 4
        for (int e = 0; e < EPB; e++) {
            int i = ii_s[e];
            if (i != iprev) {
                atomicAdd(&out_x[(size_t)iprev * FF + f], run);
                run = 0.f; iprev = i;
            }
            float a = alpha_s[e][hh] * cut_s[e];
            run = fmaf(a, __ldg(&g_v[(size_t)jj_s[e] * FF + f]), run);
        }
        atomicAdd(&out_x[(size_t)iprev * FF + f], run);
    }
    // ---- scatter ev_att
    if (tid < NORD) {
        int o  = tid;
        int hh = (o < 3) ? 4 : ((o < 8) ? 5 : 6);
        float run = 0.f;
        int iprev = ii_s[0];
        for (int e = 0; e < EPB; e++) {
            int i = ii_s[e];
            if (i != iprev) {
                atomicAdd(&out_ev[(size_t)iprev * NORD + o], run);
                run = 0.f; iprev = i;
            }
            run = fmaf(alpha_s[e][hh] * cut_s[e], ylm_s[e][o], run);
        }
        atomicAdd(&out_ev[(size_t)iprev * NORD + o], run);
    }
}

extern "C" void kernel_launch(void* const* d_in, const int* in_sizes, int n_in,
                              void* d_out, int out_size) {
    const float* x     = (const float*)d_in[0];
    const float* ev    = (const float*)d_in[1];
    const float* rbf   = (const float*)d_in[2];
    const float* ylm   = (const float*)d_in[3];
    const float* cut   = (const float*)d_in[4];
    const int*   idx_i = (const int*)d_in[5];
    const int*   idx_j = (const int*)d_in[6];
    const float* W1r   = (const float*)d_in[7];
    const float* b1r   = (const float*)d_in[8];
    const float* W2r   = (const float*)d_in[9];
    const float* b2r   = (const float*)d_in[10];
    const float* W1s   = (const float*)d_in[11];
    const float* b1s   = (const float*)d_in[12];
    const float* W2s   = (const float*)d_in[13];
    const float* b2s   = (const float*)d_in[14];
    const float* Wq    = (const float*)d_in[15];
    const float* Wk    = (const float*)d_in[16];
    const float* Wv    = (const float*)d_in[17];

    float* out    = (float*)d_out;
    float* out_x  = out;                       // [N,224]
    float* out_ev = out + (size_t)NN * FF;     // [N,15]

    const int dynsmem = (CT * FF + FF * HP) * (int)sizeof(float);
    cudaFuncSetAttribute(edge_kernel, cudaFuncAttributeMaxDynamicSharedMemorySize, dynsmem);

    // 1) per-node q,k,v + zero outputs
    node_kernel<<<NN, 224>>>(x, Wq, Wk, Wv, out_x, out_ev);

    // 2) edges
    edge_kernel<<<PP / EPB, TPB, dynsmem>>>(
        rbf, ylm, cut, idx_i, idx_j, ev,
        W1r, b1r, W2r, b2r, W1s, b1s, W2s, b2s,
        out_x, out_ev);
}

// round 11
// speedup vs baseline: 1.4082x; 1.4082x over previous
#include <cuda_runtime.h>
#include <cuda_bf16.h>

// Problem constants (fixed shapes from reference)
#define NN 25000
#define PP 400000
#define FF 224      // = TF = TH*FH
#define KK 32
#define HH 4
#define THH 7
#define DV 56
#define NORD 15

#define EPB 32     // edges per block
#define TPB 224    // threads per block (edge kernel)
#define CT 32      // c-tile rows staged in smem
#define HP 33      // Hs row pitch: stride-33 => conflict-free for both
                   // writer (stride 33 == 1 mod 32) and reader (stride 1)

// -------- scratch (static device arrays; no allocation allowed) --------
__device__ float g_q[NN * FF];
__device__ float g_k[NN * FF];
__device__ float g_v[NN * FF];

__device__ __forceinline__ float silu_f(float x) {
    return x / (1.0f + __expf(-x));
}

// -------- per-node q,k,v precompute + output zeroing --------
__global__ __launch_bounds__(224) void node_kernel(
    const float* __restrict__ x,
    const float* __restrict__ Wq,
    const float* __restrict__ Wk,
    const float* __restrict__ Wv,
    float* __restrict__ out_x,
    float* __restrict__ out_ev)
{
    __shared__ float xs[FF];
    int n = blockIdx.x;
    int f = threadIdx.x;
    xs[f] = x[n * FF + f];
    // zero outputs (atomics accumulate into them later)
    out_x[(size_t)n * FF + f] = 0.0f;
    if (f < NORD) out_ev[(size_t)n * NORD + f] = 0.0f;
    __syncthreads();

    // q / k
    {
        int t = f >> 5;
        int i = f & 31;
        const float* wq = Wq + (t * 32 + i) * 32;
        const float* wk = Wk + (t * 32 + i) * 32;
        const float* xb = xs + t * 32;
        float aq = 0.f, ak = 0.f;
#pragma unroll
        for (int j = 0; j < 32; j++) {
            float xv = xb[j];
            aq = fmaf(__ldg(&wq[j]), xv, aq);
            ak = fmaf(__ldg(&wk[j]), xv, ak);
        }
        g_q[n * FF + f] = silu_f(aq);
        g_k[n * FF + f] = silu_f(ak);
    }
    // v
    {
        int h = f / DV;
        int i = f % DV;
        const float* wv = Wv + (h * DV + i) * DV;
        const float* xb = xs + h * DV;
        float av = 0.f;
#pragma unroll 8
        for (int j = 0; j < DV; j++) av = fmaf(__ldg(&wv[j]), xb[j], av);
        g_v[n * FF + f] = av;
    }
}

// -------- edge kernel --------
// dyn smem: w2s [CT][224] then Hs [224][HP]
extern "C" __global__ void __launch_bounds__(TPB, 3) edge_kernel(
    const float* __restrict__ rbf,
    const float* __restrict__ ylm,
    const float* __restrict__ cut,
    const int*   __restrict__ idx_i,
    const int*   __restrict__ idx_j,
    const float* __restrict__ ev,
    const float* __restrict__ W1r, const float* __restrict__ b1r,
    const float* __restrict__ W2r, const float* __restrict__ b2r,
    const float* __restrict__ W1s, const float* __restrict__ b1s,
    const float* __restrict__ W2s, const float* __restrict__ b2s,
    float* __restrict__ out_x, float* __restrict__ out_ev)
{
    extern __shared__ float dyn[];
    float* w2s = dyn;                 // CT * FF
    float* Hs  = dyn + CT * FF;       // 224 * HP  (c-major, pitch 33)

    __shared__ float rbfc[EPB][KK];
    __shared__ float con_s[EPB][3];
    __shared__ float alpha_s[EPB][THH];
    __shared__ float ylm_s[EPB][NORD];
    __shared__ int   ii_s[EPB], jj_s[EPB];
    __shared__ float cut_s[EPB];

    const int tid = threadIdx.x;
    const int p0  = blockIdx.x * EPB;

    if (tid < EPB) {
        int p = p0 + tid;
        ii_s[tid]  = idx_i[p];
        jj_s[tid]  = idx_j[p];
        cut_s[tid] = cut[p];
    }
    if (tid < EPB * THH) ((float*)alpha_s)[tid] = 0.0f;
    __syncthreads();

    // rbf * cut into smem
    for (int idx = tid; idx < EPB * KK; idx += TPB) {
        int e = idx >> 5, kk = idx & 31;
        rbfc[e][kk] = rbf[(p0 + e) * KK + kk] * cut_s[e];
    }
    // ylm into smem
    for (int idx = tid; idx < EPB * NORD; idx += TPB) {
        int e = idx / NORD, o = idx % NORD;
        ylm_s[e][o] = ylm[(p0 + e) * NORD + o];
    }
    // l0 contraction per edge
    if (tid < EPB) {
        int e = tid;
        const float* evi = ev + (size_t)ii_s[e] * NORD;
        const float* evj = ev + (size_t)jj_s[e] * NORD;
        float c0 = 0.f, c1 = 0.f, c2 = 0.f;
#pragma unroll
        for (int o = 0; o < 3; o++)  { float d = __ldg(&evj[o]) - __ldg(&evi[o]); c0 = fmaf(d, d, c0); }
#pragma unroll
        for (int o = 3; o < 8; o++)  { float d = __ldg(&evj[o]) - __ldg(&evi[o]); c1 = fmaf(d, d, c1); }
#pragma unroll
        for (int o = 8; o < 15; o++) { float d = __ldg(&evj[o]) - __ldg(&evi[o]); c2 = fmaf(d, d, c2); }
        con_s[e][0] = c0; con_s[e][1] = c1; con_s[e][2] = c2;
    }
    __syncthreads();

    // ---- H compute ----
    // Thread owns fixed c = tid % 112; visits 16 edges (e = 2k + (tid>=112)).
    // Writes Hs[c][e] with pitch 33: lanes have consecutive c -> stride 33 mod 32 = 1,
    // conflict-free STS.
    {
        const int cH = tid % 112;
        const int eBase = (tid >= 112) ? 1 : 0;
        float w1rr[32];
#pragma unroll
        for (int kk = 0; kk < 32; kk++) w1rr[kk] = __ldg(&W1r[kk * 112 + cH]);
        const float w1s0 = __ldg(&W1s[cH]);
        const float w1s1 = __ldg(&W1s[112 + cH]);
        const float w1s2 = __ldg(&W1s[224 + cH]);
        const float b1rc = __ldg(&b1r[cH]);
        const float b1sc = __ldg(&b1s[cH]);
#pragma unroll 4
        for (int k2 = 0; k2 < 16; k2++) {
            const int e = 2 * k2 + eBase;
            const float4* r4 = (const float4*)&rbfc[e][0];
            float a1 = b1rc;
#pragma unroll
            for (int q = 0; q < 8; q++) {
                float4 rv = r4[q];
                a1 = fmaf(rv.x, w1rr[4 * q + 0], a1);
                a1 = fmaf(rv.y, w1rr[4 * q + 1], a1);
                a1 = fmaf(rv.z, w1rr[4 * q + 2], a1);
                a1 = fmaf(rv.w, w1rr[4 * q + 3], a1);
            }
            float a2 = b1sc;
            a2 = fmaf(con_s[e][0], w1s0, a2);
            a2 = fmaf(con_s[e][1], w1s1, a2);
            a2 = fmaf(con_s[e][2], w1s2, a2);
            Hs[cH * HP + e]         = silu_f(a1);
            Hs[(cH + 112) * HP + e] = silu_f(a2);
        }
    }

    // ---- main trilinear: wsum[e, f] = sum_c H[e,c] * W2cat[c,f] ----
    // Warp remap: lane = edge (0..31), warp owns 4 column-chunks
    // (f0 = warp*16 + k*4, k=0..3, covering cols f0 and f0+112).
    // w2s reads are warp-uniform -> smem broadcast; H reads stride-1 -> conflict-free.
    const int warp = tid >> 5;        // 0..6
    const int lane = tid & 31;        // = edge index

    float acc[4][8];
    {
#pragma unroll
        for (int k = 0; k < 4; k++) {
            int f0 = warp * 16 + k * 4;
#pragma unroll
            for (int u = 0; u < 4; u++) {
                acc[k][u]     = __ldg(&b2r[f0 + u])       + __ldg(&b2s[f0 + u]);
                acc[k][4 + u] = __ldg(&b2r[f0 + 112 + u]) + __ldg(&b2s[f0 + 112 + u]);
            }
        }
    }

#pragma unroll 1
    for (int ct = 0; ct < FF / CT; ct++) {
        __syncthreads();   // w2s reuse + (first iter) Hs completion
        // stage W2cat rows [ct*CT, ct*CT+CT) — float4 vectorized
        for (int idx = tid; idx < CT * (FF / 4); idx += TPB) {
            int cl = idx / (FF / 4);
            int f4 = idx % (FF / 4);
            int cg = ct * CT + cl;
            const float4* src = (cg < 112)
                ? (const float4*)(W2r + (size_t)cg * FF)
                : (const float4*)(W2s + (size_t)(cg - 112) * FF);
            ((float4*)(w2s + cl * FF))[f4] = __ldg(&src[f4]);
        }
        __syncthreads();
        const float* hptr = Hs + (ct * CT) * HP + lane;
        const float* wb   = w2s + warp * 16;
#pragma unroll 4
        for (int cl = 0; cl < CT; cl++) {
            const float h = hptr[cl * HP];
            const float* wrow = wb + cl * FF;
            float4 wA0 = *(const float4*)(wrow);
            float4 wB0 = *(const float4*)(wrow + 112);
            float4 wA1 = *(const float4*)(wrow + 4);
            float4 wB1 = *(const float4*)(wrow + 116);
            float4 wA2 = *(const float4*)(wrow + 8);
            float4 wB2 = *(const float4*)(wrow + 120);
            float4 wA3 = *(const float4*)(wrow + 12);
            float4 wB3 = *(const float4*)(wrow + 124);
            acc[0][0] = fmaf(h, wA0.x, acc[0][0]);
            acc[0][1] = fmaf(h, wA0.y, acc[0][1]);
            acc[0][2] = fmaf(h, wA0.z, acc[0][2]);
            acc[0][3] = fmaf(h, wA0.w, acc[0][3]);
            acc[0][4] = fmaf(h, wB0.x, acc[0][4]);
            acc[0][5] = fmaf(h, wB0.y, acc[0][5]);
            acc[0][6] = fmaf(h, wB0.z, acc[0][6]);
            acc[0][7] = fmaf(h, wB0.w, acc[0][7]);
            acc[1][0] = fmaf(h, wA1.x, acc[1][0]);
            acc[1][1] = fmaf(h, wA1.y, acc[1][1]);
            acc[1][2] = fmaf(h, wA1.z, acc[1][2]);
            acc[1][3] = fmaf(h, wA1.w, acc[1][3]);
            acc[1][4] = fmaf(h, wB1.x, acc[1][4]);
            acc[1][5] = fmaf(h, wB1.y, acc[1][5]);
            acc[1][6] = fmaf(h, wB1.z, acc[1][6]);
            acc[1][7] = fmaf(h, wB1.w, acc[1][7]);
            acc[2][0] = fmaf(h, wA2.x, acc[2][0]);
            acc[2][1] = fmaf(h, wA2.y, acc[2][1]);
            acc[2][2] = fmaf(h, wA2.z, acc[2][2]);
            acc[2][3] = fmaf(h, wA2.w, acc[2][3]);
            acc[2][4] = fmaf(h, wB2.x, acc[2][4]);
            acc[2][5] = fmaf(h, wB2.y, acc[2][5]);
            acc[2][6] = fmaf(h, wB2.z, acc[2][6]);
            acc[2][7] = fmaf(h, wB2.w, acc[2][7]);
            acc[3][0] = fmaf(h, wA3.x, acc[3][0]);
            acc[3][1] = fmaf(h, wA3.y, acc[3][1]);
            acc[3][2] = fmaf(h, wA3.z, acc[3][2]);
            acc[3][3] = fmaf(h, wA3.w, acc[3][3]);
            acc[3][4] = fmaf(h, wB3.x, acc[3][4]);
            acc[3][5] = fmaf(h, wB3.y, acc[3][5]);
            acc[3][6] = fmaf(h, wB3.z, acc[3][6]);
            acc[3][7] = fmaf(h, wB3.w, acc[3][7]);
        }
    }

    // ---- apply G = q_i * k_j elementwise; thread owns edge = lane ----
    {
        const size_t ri = (size_t)ii_s[lane] * FF;
        const size_t rj = (size_t)jj_s[lane] * FF;
#pragma unroll
        for (int k = 0; k < 4; k++) {
            const int f0 = warp * 16 + k * 4;
            float4 qa = *(const float4*)&g_q[ri + f0];
            float4 qb = *(const float4*)&g_q[ri + f0 + 112];
            float4 ka = *(const float4*)&g_k[rj + f0];
            float4 kb = *(const float4*)&g_k[rj + f0 + 112];
            float aA = acc[k][0] * (qa.x * ka.x);
            aA = fmaf(acc[k][1], qa.y * ka.y, aA);
            aA = fmaf(acc[k][2], qa.z * ka.z, aA);
            aA = fmaf(acc[k][3], qa.w * ka.w, aA);
            float aB = acc[k][4] * (qb.x * kb.x);
            aB = fmaf(acc[k][5], qb.y * kb.y, aB);
            aB = fmaf(acc[k][6], qb.z * kb.z, aB);
            aB = fmaf(acc[k][7], qb.w * kb.w, aB);
            atomicAdd(&alpha_s[lane][f0 >> 5], aA);
            atomicAdd(&alpha_s[lane][(f0 + 112) >> 5], aB);
        }
    }
    __syncthreads();

    // ---- scatter x_att: thread f owns output column f; run-length aggregate over sorted i
    {
        int f = tid;                 // 0..223
        int hh = f / DV;             // 0..3
        float run = 0.f;
        int iprev = ii_s[0];
#pragma unroll 4
        for (int e = 0; e < EPB; e++) {
            int i = ii_s[e];
            if (i != iprev) {
                atomicAdd(&out_x[(size_t)iprev * FF + f], run);
                run = 0.f; iprev = i;
            }
            float a = alpha_s[e][hh] * cut_s[e];
            run = fmaf(a, __ldg(&g_v[(size_t)jj_s[e] * FF + f]), run);
        }
        atomicAdd(&out_x[(size_t)iprev * FF + f], run);
    }
    // ---- scatter ev_att
    if (tid < NORD) {
        int o  = tid;
        int hh = (o < 3) ? 4 : ((o < 8) ? 5 : 6);
        float run = 0.f;
        int iprev = ii_s[0];
        for (int e = 0; e < EPB; e++) {
            int i = ii_s[e];
            if (i != iprev) {
                atomicAdd(&out_ev[(size_t)iprev * NORD + o], run);
                run = 0.f; iprev = i;
            }
            run = fmaf(alpha_s[e][hh] * cut_s[e], ylm_s[e][o], run);
        }
        atomicAdd(&out_ev[(size_t)iprev * NORD + o], run);
    }
}

extern "C" void kernel_launch(void* const* d_in, const int* in_sizes, int n_in,
                              void* d_out, int out_size) {
    const float* x     = (const float*)d_in[0];
    const float* ev    = (const float*)d_in[1];
    const float* rbf   = (const float*)d_in[2];
    const float* ylm   = (const float*)d_in[3];
    const float* cut   = (const float*)d_in[4];
    const int*   idx_i = (const int*)d_in[5];
    const int*   idx_j = (const int*)d_in[6];
    const float* W1r   = (const float*)d_in[7];
    const float* b1r   = (const float*)d_in[8];
    const float* W2r   = (const float*)d_in[9];
    const float* b2r   = (const float*)d_in[10];
    const float* W1s   = (const float*)d_in[11];
    const float* b1s   = (const float*)d_in[12];
    const float* W2s   = (const float*)d_in[13];
    const float* b2s   = (const float*)d_in[14];
    const float* Wq    = (const float*)d_in[15];
    const float* Wk    = (const float*)d_in[16];
    const float* Wv    = (const float*)d_in[17];

    float* out    = (float*)d_out;
    float* out_x  = out;                       // [N,224]
    float* out_ev = out + (size_t)NN * FF;     // [N,15]

    const int dynsmem = (CT * FF + FF * HP) * (int)sizeof(float);
    cudaFuncSetAttribute(edge_kernel, cudaFuncAttributeMaxDynamicSharedMemorySize, dynsmem);

    // 1) per-node q,k,v + zero outputs
    node_kernel<<<NN, 224>>>(x, Wq, Wk, Wv, out_x, out_ev);

    // 2) edges
    edge_kernel<<<PP / EPB, TPB, dynsmem>>>(
        rbf, ylm, cut, idx_i, idx_j, ev,
        W1r, b1r, W2r, b2r, W1s, b1s, W2s, b2s,
        out_x, out_ev);
}